// round 7
// baseline (speedup 1.0000x reference)
#include <cuda_runtime.h>
#include <cuda_fp16.h>
#include <cstdint>

#define D     512
#define NTR   16384
#define NT    8192
#define NCLS  16

#define NSPLIT  8
#define JCHUNK  (NTR / NSPLIT)       // 2048
#define SCHUNK  256                  // j staged per buffer
#define NSC     (JCHUNK / SCHUNK)    // 8
#define KSTEPS  (SCHUNK / 16)        // 16 mma k-steps per staged chunk
#define MTILE   64                   // i rows per CTA (4 warps x 16)
#define YSTR    24                   // halves per padded ytr row (48B, conflict-free ldmatrix)

#define LOG2E  1.4426950408889634f

#define PROJ_CTAS ((NT + NTR) / 8)     // 3072
#define PREP_CTAS (NTR / 256)          // 64

// ---------------- device scratch ----------------
__device__ float2 g_q[NT];          // q pre-scaled by log2(e)
__device__ float2 g_k[NTR];
__device__ uint4  g_y16[NTR * 2];   // fp16 ytr, 32B per row
__device__ float  g_pnum[NSPLIT * NT * NCLS];
__device__ float  g_pden[NSPLIT * NT];
__device__ int    g_maxk;           // bits of max_j ||k_j|| (monotone across replays)

// ---------------- helpers ----------------
__device__ __forceinline__ uint32_t cvt_f16x2(float hi, float lo) {
    uint32_t r; asm("cvt.rn.f16x2.f32 %0, %1, %2;" : "=r"(r) : "f"(hi), "f"(lo)); return r;
}
__device__ __forceinline__ uint32_t ex2h2(uint32_t x) {
    uint32_t r; asm("ex2.approx.f16x2 %0, %1;" : "=r"(r) : "r"(x)); return r;
}
__device__ __forceinline__ uint32_t smem_u32(const void* p) {
    uint32_t a;
    asm("{ .reg .u64 t; cvta.to.shared.u64 t, %1; cvt.u32.u64 %0, t; }" : "=r"(a) : "l"(p));
    return a;
}
__device__ __forceinline__ void ldmatrix_x4_trans(uint32_t& r0, uint32_t& r1,
                                                  uint32_t& r2, uint32_t& r3,
                                                  uint32_t addr) {
    asm volatile("ldmatrix.sync.aligned.m8n8.x4.trans.shared.b16 {%0,%1,%2,%3}, [%4];"
                 : "=r"(r0), "=r"(r1), "=r"(r2), "=r"(r3) : "r"(addr));
}
__device__ __forceinline__ void mma16816(float& c0, float& c1, float& c2, float& c3,
                                         uint32_t a0, uint32_t a1, uint32_t a2, uint32_t a3,
                                         uint32_t b0, uint32_t b1) {
    asm volatile("mma.sync.aligned.m16n8k16.row.col.f32.f16.f16.f32 "
                 "{%0,%1,%2,%3}, {%4,%5,%6,%7}, {%8,%9}, {%0,%1,%2,%3};"
                 : "+f"(c0), "+f"(c1), "+f"(c2), "+f"(c3)
                 : "r"(a0), "r"(a1), "r"(a2), "r"(a3), "r"(b0), "r"(b1));
}

// ---------------- kernel 1: fused projections + ytr->fp16 conversion ----------------
__global__ __launch_bounds__(256) void proj_prep_kernel(const float* __restrict__ xt,
                                                        const float* __restrict__ xtr,
                                                        const float* __restrict__ A,
                                                        const float* __restrict__ ytr) {
    int tid = threadIdx.x;

    if (blockIdx.x >= PROJ_CTAS) {
        // ---- prep branch: ytr -> fp16 ----
        int row = (blockIdx.x - PROJ_CTAS) * 256 + tid;
        const float4* src = reinterpret_cast<const float4*>(ytr + (size_t)row * NCLS);
        float4 v0 = src[0], v1 = src[1], v2 = src[2], v3 = src[3];
        uint4 o0, o1;
        o0.x = cvt_f16x2(v0.y, v0.x); o0.y = cvt_f16x2(v0.w, v0.z);
        o0.z = cvt_f16x2(v1.y, v1.x); o0.w = cvt_f16x2(v1.w, v1.z);
        o1.x = cvt_f16x2(v2.y, v2.x); o1.y = cvt_f16x2(v2.w, v2.z);
        o1.z = cvt_f16x2(v3.y, v3.x); o1.w = cvt_f16x2(v3.w, v3.z);
        g_y16[row * 2]     = o0;
        g_y16[row * 2 + 1] = o1;
        return;
    }

    // ---- proj branch: q = (xt@A)*log2e, k = xtr@A ----
    // A staged transposed so float4-x access hits bank == lane (conflict-free).
    __shared__ float sA0t[D], sA1t[D];
    __shared__ int   smaxn;
    if (tid == 0) smaxn = 0;
    #pragma unroll
    for (int c = tid; c < D; c += 256) {
        float2 a = reinterpret_cast<const float2*>(A)[c];
        int idx = (c >> 7) * 128 + (c & 3) * 32 + ((c >> 2) & 31);
        sA0t[idx] = a.x; sA1t[idx] = a.y;
    }
    __syncthreads();

    int gwarp = blockIdx.x * 8 + (tid >> 5);
    int lane  = tid & 31;
    bool is_k = (gwarp >= NT);

    const float* src;  float2* dst;  int row;  float scale;
    if (!is_k) { row = gwarp;      src = xt;  dst = g_q; scale = LOG2E; }
    else       { row = gwarp - NT; src = xtr; dst = g_k; scale = 1.0f;  }

    const float4* xr4 = reinterpret_cast<const float4*>(src + (size_t)row * D);
    float s0 = 0.f, s1 = 0.f;
    #pragma unroll
    for (int it = 0; it < 4; it++) {
        float4 x = xr4[it * 32 + lane];              // LDG.128, coalesced
        int b = it * 128 + lane;
        s0 = fmaf(x.x, sA0t[b],      s0);  s1 = fmaf(x.x, sA1t[b],      s1);
        s0 = fmaf(x.y, sA0t[b + 32], s0);  s1 = fmaf(x.y, sA1t[b + 32], s1);
        s0 = fmaf(x.z, sA0t[b + 64], s0);  s1 = fmaf(x.z, sA1t[b + 64], s1);
        s0 = fmaf(x.w, sA0t[b + 96], s0);  s1 = fmaf(x.w, sA1t[b + 96], s1);
    }
    #pragma unroll
    for (int off = 16; off > 0; off >>= 1) {
        s0 += __shfl_xor_sync(0xFFFFFFFFu, s0, off);
        s1 += __shfl_xor_sync(0xFFFFFFFFu, s1, off);
    }
    if (lane == 0) {
        dst[row] = make_float2(s0 * scale, s1 * scale);
        if (is_k) {
            float nrm = sqrtf(s0 * s0 + s1 * s1);
            atomicMax(&smaxn, __float_as_int(nrm));   // positive floats: int-compare ok
        }
    }
    __syncthreads();
    if (is_k && tid == 0) atomicMax(&g_maxk, smaxn);
}

// ---------------- kernel 2: fp32 logits (row-bound shift) + f16x2 exp + mma.sync ----------------
__global__ __launch_bounds__(128, 7) void attn_kernel() {
    __shared__ float2 sk[2][SCHUNK];                         // 2 x 2KB
    __shared__ __align__(16) __half sy[2][SCHUNK * YSTR];    // 2 x 12KB (48B rows)

    int tid  = threadIdx.x;
    int wid  = tid >> 5;
    int lane = tid & 31;
    int g    = lane >> 2;
    int tg   = lane & 3;
    int split = blockIdx.y;
    int r0 = blockIdx.x * MTILE + wid * 16 + g;
    int r1 = r0 + 8;
    int j0 = split * JCHUNK;

    float2 qg = g_q[r0];
    float2 qh = g_q[r1];
    float Mk = __int_as_float(g_maxk);
    // per-row logit upper bound (log2 units): l <= ||q||*max||k||  (Cauchy-Schwarz)
    float nBg = -sqrtf(qg.x * qg.x + qg.y * qg.y) * Mk;
    float nBh = -sqrtf(qh.x * qh.x + qh.y * qh.y) * Mk;

    // accumulators: classes n0-7, n8-15, denominator (ones-column MMA)
    float d10 = 0, d11 = 0, d12 = 0, d13 = 0;
    float d20 = 0, d21 = 0, d22 = 0, d23 = 0;
    float e0 = 0, e1 = 0, e2 = 0, e3 = 0;
    const uint32_t ONES = 0x3C003C00u;

    // prefetch registers for staging
    float4 pk;  uint4 py0, py1, py2, py3;

#define LDG_CHUNK(sc) do {                                                   \
        int jb = j0 + (sc) * SCHUNK;                                         \
        pk = reinterpret_cast<const float4*>(g_k)[(jb >> 1) + tid];          \
        int rr = (jb + 2 * tid) * 2;                                         \
        py0 = g_y16[rr]; py1 = g_y16[rr + 1];                                \
        py2 = g_y16[rr + 2]; py3 = g_y16[rr + 3];                            \
    } while (0)

#define STS_CHUNK(b) do {                                                    \
        reinterpret_cast<float4*>(sk[b])[tid] = pk;                          \
        uint4* dr0 = reinterpret_cast<uint4*>(&sy[b][(2 * tid) * YSTR]);     \
        dr0[0] = py0; dr0[1] = py1;                                          \
        uint4* dr1 = reinterpret_cast<uint4*>(&sy[b][(2 * tid + 1) * YSTR]); \
        dr1[0] = py2; dr1[1] = py3;                                          \
    } while (0)

    LDG_CHUNK(0);
    STS_CHUNK(0);
    LDG_CHUNK(1);
    __syncthreads();

    for (int sc = 0; sc < NSC; sc++) {
        int b = sc & 1;
        const float4* k4 = reinterpret_cast<const float4*>(sk[b]);
        uint32_t ybase = smem_u32(&sy[b][(lane & 15) * YSTR]) + (lane >> 4) * 16;

        #pragma unroll 4
        for (int ks = 0; ks < KSTEPS; ks++) {
            // k values: j = ks*16 + {2tg,2tg+1} and +8 (broadcast LDS)
            float4 ka = k4[ks * 8 + tg];
            float4 kb = k4[ks * 8 + 4 + tg];

            // shifted fp32 logits: l' = q.k - B_row <= 0 (no overflow possible)
            float lg0 = fmaf(qg.x, ka.x, fmaf(qg.y, ka.y, nBg));
            float lg1 = fmaf(qg.x, ka.z, fmaf(qg.y, ka.w, nBg));
            float lg2 = fmaf(qg.x, kb.x, fmaf(qg.y, kb.y, nBg));
            float lg3 = fmaf(qg.x, kb.z, fmaf(qg.y, kb.w, nBg));
            float lh0 = fmaf(qh.x, ka.x, fmaf(qh.y, ka.y, nBh));
            float lh1 = fmaf(qh.x, ka.z, fmaf(qh.y, ka.w, nBh));
            float lh2 = fmaf(qh.x, kb.x, fmaf(qh.y, kb.y, nBh));
            float lh3 = fmaf(qh.x, kb.z, fmaf(qh.y, kb.w, nBh));

            // pack to f16x2, packed exp -> A fragments
            uint32_t a0 = ex2h2(cvt_f16x2(lg1, lg0));
            uint32_t a1 = ex2h2(cvt_f16x2(lh1, lh0));
            uint32_t a2 = ex2h2(cvt_f16x2(lg3, lg2));
            uint32_t a3 = ex2h2(cvt_f16x2(lh3, lh2));

            uint32_t b0, b1, b2, b3;
            ldmatrix_x4_trans(b0, b1, b2, b3, ybase + (ks * 16) * (YSTR * 2));

            mma16816(d10, d11, d12, d13, a0, a1, a2, a3, b0, b1);   // classes 0-7
            mma16816(d20, d21, d22, d23, a0, a1, a2, a3, b2, b3);   // classes 8-15
            mma16816(e0, e1, e2, e3, a0, a1, a2, a3, ONES, ONES);   // denominator
        }

        if (sc + 1 < NSC) {
            STS_CHUNK(b ^ 1);
            if (sc + 2 < NSC) LDG_CHUNK(sc + 2);
        }
        __syncthreads();
    }

    // write partials (shift B_row is split-independent -> partials add; B cancels in num/den)
    float* p0 = &g_pnum[((size_t)split * NT + r0) * NCLS];
    float* p1 = &g_pnum[((size_t)split * NT + r1) * NCLS];
    *reinterpret_cast<float2*>(p0 + 2 * tg)     = make_float2(d10, d11);
    *reinterpret_cast<float2*>(p0 + 8 + 2 * tg) = make_float2(d20, d21);
    *reinterpret_cast<float2*>(p1 + 2 * tg)     = make_float2(d12, d13);
    *reinterpret_cast<float2*>(p1 + 8 + 2 * tg) = make_float2(d22, d23);
    if (tg == 0) {
        g_pden[(size_t)split * NT + r0] = e0;
        g_pden[(size_t)split * NT + r1] = e2;
    }
#undef LDG_CHUNK
#undef STS_CHUNK
}

// ---------------- kernel 3: reduce splits + normalize (thread per i x class-quad) ----------------
__global__ __launch_bounds__(256) void reduce_kernel(float* __restrict__ out) {
    int idx = blockIdx.x * 256 + threadIdx.x;     // 0 .. NT*4-1
    int i   = idx >> 2;
    int tg  = idx & 3;

    float4 n = make_float4(0, 0, 0, 0);
    float d = 0.f;
    #pragma unroll
    for (int s = 0; s < NSPLIT; s++) {
        float4 a = *reinterpret_cast<const float4*>(
            &g_pnum[((size_t)s * NT + i) * NCLS + tg * 4]);
        n.x += a.x; n.y += a.y; n.z += a.z; n.w += a.w;
        d += g_pden[(size_t)s * NT + i];
    }
    float inv = 1.0f / d;
    n.x *= inv; n.y *= inv; n.z *= inv; n.w *= inv;
    *reinterpret_cast<float4*>(out + (size_t)i * NCLS + tg * 4) = n;
}

// ---------------- launch ----------------
extern "C" void kernel_launch(void* const* d_in, const int* in_sizes, int n_in,
                              void* d_out, int out_size) {
    const float* xtr = (const float*)d_in[0];   // [16384, 512]
    const float* ytr = (const float*)d_in[1];   // [16384, 16]
    const float* xt  = (const float*)d_in[2];   // [8192, 512]
    const float* A   = (const float*)d_in[3];   // [512, 2]
    float* out = (float*)d_out;                 // [8192, 16]

    proj_prep_kernel<<<PROJ_CTAS + PREP_CTAS, 256>>>(xt, xtr, A, ytr);

    dim3 grid(NT / MTILE, NSPLIT);               // 128 x 8 = 1024 CTAs
    attn_kernel<<<grid, 128>>>();

    reduce_kernel<<<NT * 4 / 256, 256>>>(out);   // 128 CTAs
}

// round 8
// speedup vs baseline: 1.0959x; 1.0959x over previous
#include <cuda_runtime.h>
#include <cuda_fp16.h>
#include <cstdint>

#define D     512
#define NTR   16384
#define NT    8192
#define NCLS  16

#define NSPLIT  8
#define JCHUNK  (NTR / NSPLIT)       // 2048
#define SCHUNK  256                  // j staged per buffer
#define NSC     (JCHUNK / SCHUNK)    // 8
#define KSTEPS  (SCHUNK / 16)        // 16 mma k-steps per staged chunk
#define MTILE   64                   // i rows per CTA (4 warps x 16)
#define YSTR    24                   // halves per padded ytr row (48B, conflict-free ldmatrix)

#define LOG2E  1.4426950408889634f
#define MS2    (-8.656170245333781f)   // -6 nats in log2 units, softmax-invariant shift

#define RPW       4                    // rows per warp in proj
#define PROJ_CTAS ((NT + NTR) / (8 * RPW))   // 768
#define PREP_CTAS (NTR / 256)                // 64

// ---------------- device scratch ----------------
__device__ float2 g_q[NT];          // q pre-scaled by log2(e)
__device__ float2 g_k[NTR];
__device__ uint4  g_y16[NTR * 2];   // fp16 ytr, 32B per row
__device__ float  g_pnum[NSPLIT * NT * NCLS];
__device__ float  g_pden[NSPLIT * NT];

// ---------------- helpers ----------------
__device__ __forceinline__ float ex2f(float x) {
    float r; asm("ex2.approx.ftz.f32 %0, %1;" : "=f"(r) : "f"(x)); return r;
}
__device__ __forceinline__ uint32_t cvt_f16x2(float hi, float lo) {
    uint32_t r; asm("cvt.rn.f16x2.f32 %0, %1, %2;" : "=r"(r) : "f"(hi), "f"(lo)); return r;
}
__device__ __forceinline__ uint32_t smem_u32(const void* p) {
    uint32_t a;
    asm("{ .reg .u64 t; cvta.to.shared.u64 t, %1; cvt.u32.u64 %0, t; }" : "=r"(a) : "l"(p));
    return a;
}
__device__ __forceinline__ void ldmatrix_x4_trans(uint32_t& r0, uint32_t& r1,
                                                  uint32_t& r2, uint32_t& r3,
                                                  uint32_t addr) {
    asm volatile("ldmatrix.sync.aligned.m8n8.x4.trans.shared.b16 {%0,%1,%2,%3}, [%4];"
                 : "=r"(r0), "=r"(r1), "=r"(r2), "=r"(r3) : "r"(addr));
}
__device__ __forceinline__ void mma16816(float& c0, float& c1, float& c2, float& c3,
                                         uint32_t a0, uint32_t a1, uint32_t a2, uint32_t a3,
                                         uint32_t b0, uint32_t b1) {
    asm volatile("mma.sync.aligned.m16n8k16.row.col.f32.f16.f16.f32 "
                 "{%0,%1,%2,%3}, {%4,%5,%6,%7}, {%8,%9}, {%0,%1,%2,%3};"
                 : "+f"(c0), "+f"(c1), "+f"(c2), "+f"(c3)
                 : "r"(a0), "r"(a1), "r"(a2), "r"(a3), "r"(b0), "r"(b1));
}

// ---------------- kernel 1: fused projections + ytr->fp16 conversion ----------------
// CTAs [0, PROJ_CTAS): 8 warps x 4 rows each (32 rows/CTA). q CTAs: [0,256), k CTAs: [256,768).
// CTAs [PROJ_CTAS, +PREP_CTAS): convert 256 ytr rows to fp16.
__global__ __launch_bounds__(256) void proj_prep_kernel(const float* __restrict__ xt,
                                                        const float* __restrict__ xtr,
                                                        const float* __restrict__ A,
                                                        const float* __restrict__ ytr) {
    int tid = threadIdx.x;

    if (blockIdx.x >= PROJ_CTAS) {
        // ---- prep branch: ytr -> fp16 ----
        int row = (blockIdx.x - PROJ_CTAS) * 256 + tid;
        const float4* src = reinterpret_cast<const float4*>(ytr + (size_t)row * NCLS);
        float4 v0 = src[0], v1 = src[1], v2 = src[2], v3 = src[3];
        uint4 o0, o1;
        o0.x = cvt_f16x2(v0.y, v0.x); o0.y = cvt_f16x2(v0.w, v0.z);
        o0.z = cvt_f16x2(v1.y, v1.x); o0.w = cvt_f16x2(v1.w, v1.z);
        o1.x = cvt_f16x2(v2.y, v2.x); o1.y = cvt_f16x2(v2.w, v2.z);
        o1.z = cvt_f16x2(v3.y, v3.x); o1.w = cvt_f16x2(v3.w, v3.z);
        g_y16[row * 2]     = o0;
        g_y16[row * 2 + 1] = o1;
        return;
    }

    // ---- proj branch: q = (xt@A)*log2e, k = xtr@A ----
    // A staged transposed so the per-lane column slice hits bank == lane (conflict-free).
    __shared__ float sA0t[D], sA1t[D];
    #pragma unroll
    for (int c = tid; c < D; c += 256) {
        float2 a = reinterpret_cast<const float2*>(A)[c];
        int idx = (c >> 7) * 128 + (c & 3) * 32 + ((c >> 2) & 31);
        sA0t[idx] = a.x; sA1t[idx] = a.y;
    }
    __syncthreads();

    int warp = tid >> 5;
    int lane = tid & 31;
    int row0 = blockIdx.x * (8 * RPW) + warp * RPW;

    const float* src;  float2* dst;  float scale;
    if (row0 < NT) { src = xt;  dst = g_q; scale = LOG2E; }
    else           { src = xtr; dst = g_k; scale = 1.0f;  row0 -= NT; }

    // hoist this lane's A slice into registers (reused across RPW rows)
    float a0[16], a1[16];
    #pragma unroll
    for (int it = 0; it < 4; it++) {
        #pragma unroll
        for (int u = 0; u < 4; u++) {
            int idx = it * 128 + u * 32 + lane;
            a0[it * 4 + u] = sA0t[idx];
            a1[it * 4 + u] = sA1t[idx];
        }
    }

    #pragma unroll
    for (int r = 0; r < RPW; r++) {
        const float4* xr4 = reinterpret_cast<const float4*>(src + (size_t)(row0 + r) * D);
        float4 x0 = xr4[lane];
        float4 x1 = xr4[32 + lane];
        float4 x2 = xr4[64 + lane];
        float4 x3 = xr4[96 + lane];

        float s0, s1;
        s0 =      x0.x * a0[0];            s1 =      x0.x * a1[0];
        s0 = fmaf(x0.y, a0[1],  s0);       s1 = fmaf(x0.y, a1[1],  s1);
        s0 = fmaf(x0.z, a0[2],  s0);       s1 = fmaf(x0.z, a1[2],  s1);
        s0 = fmaf(x0.w, a0[3],  s0);       s1 = fmaf(x0.w, a1[3],  s1);
        s0 = fmaf(x1.x, a0[4],  s0);       s1 = fmaf(x1.x, a1[4],  s1);
        s0 = fmaf(x1.y, a0[5],  s0);       s1 = fmaf(x1.y, a1[5],  s1);
        s0 = fmaf(x1.z, a0[6],  s0);       s1 = fmaf(x1.z, a1[6],  s1);
        s0 = fmaf(x1.w, a0[7],  s0);       s1 = fmaf(x1.w, a1[7],  s1);
        s0 = fmaf(x2.x, a0[8],  s0);       s1 = fmaf(x2.x, a1[8],  s1);
        s0 = fmaf(x2.y, a0[9],  s0);       s1 = fmaf(x2.y, a1[9],  s1);
        s0 = fmaf(x2.z, a0[10], s0);       s1 = fmaf(x2.z, a1[10], s1);
        s0 = fmaf(x2.w, a0[11], s0);       s1 = fmaf(x2.w, a1[11], s1);
        s0 = fmaf(x3.x, a0[12], s0);       s1 = fmaf(x3.x, a1[12], s1);
        s0 = fmaf(x3.y, a0[13], s0);       s1 = fmaf(x3.y, a1[13], s1);
        s0 = fmaf(x3.z, a0[14], s0);       s1 = fmaf(x3.z, a1[14], s1);
        s0 = fmaf(x3.w, a0[15], s0);       s1 = fmaf(x3.w, a1[15], s1);

        #pragma unroll
        for (int off = 16; off > 0; off >>= 1) {
            s0 += __shfl_xor_sync(0xFFFFFFFFu, s0, off);
            s1 += __shfl_xor_sync(0xFFFFFFFFu, s1, off);
        }
        if (lane == 0) dst[row0 + r] = make_float2(s0 * scale, s1 * scale);
    }
}

// ---------------- kernel 2: fp32 logits + fp32 exp + mma.sync streaming (round-4 body) ----------------
__global__ __launch_bounds__(128, 7) void attn_kernel() {
    __shared__ float2 sk[2][SCHUNK];                         // 2 x 2KB
    __shared__ __align__(16) __half sy[2][SCHUNK * YSTR];    // 2 x 12KB (48B rows)

    int tid  = threadIdx.x;
    int wid  = tid >> 5;
    int lane = tid & 31;
    int g    = lane >> 2;
    int tg   = lane & 3;
    int split = blockIdx.y;
    int r0 = blockIdx.x * MTILE + wid * 16 + g;
    int r1 = r0 + 8;
    int j0 = split * JCHUNK;

    float2 qg = g_q[r0];
    float2 qh = g_q[r1];

    // accumulators: classes n0-7, n8-15, denominator (ones-column MMA)
    float d10 = 0, d11 = 0, d12 = 0, d13 = 0;
    float d20 = 0, d21 = 0, d22 = 0, d23 = 0;
    float e0 = 0, e1 = 0, e2 = 0, e3 = 0;
    const uint32_t ONES = 0x3C003C00u;

    // prefetch registers for staging
    float4 pk;  uint4 py0, py1, py2, py3;

#define LDG_CHUNK(sc) do {                                                   \
        int jb = j0 + (sc) * SCHUNK;                                         \
        pk = reinterpret_cast<const float4*>(g_k)[(jb >> 1) + tid];          \
        int rr = (jb + 2 * tid) * 2;                                         \
        py0 = g_y16[rr]; py1 = g_y16[rr + 1];                                \
        py2 = g_y16[rr + 2]; py3 = g_y16[rr + 3];                            \
    } while (0)

#define STS_CHUNK(b) do {                                                    \
        reinterpret_cast<float4*>(sk[b])[tid] = pk;                          \
        uint4* dr0 = reinterpret_cast<uint4*>(&sy[b][(2 * tid) * YSTR]);     \
        dr0[0] = py0; dr0[1] = py1;                                          \
        uint4* dr1 = reinterpret_cast<uint4*>(&sy[b][(2 * tid + 1) * YSTR]); \
        dr1[0] = py2; dr1[1] = py3;                                          \
    } while (0)

    LDG_CHUNK(0);
    STS_CHUNK(0);
    LDG_CHUNK(1);
    __syncthreads();

    for (int sc = 0; sc < NSC; sc++) {
        int b = sc & 1;
        const float4* k4 = reinterpret_cast<const float4*>(sk[b]);
        uint32_t ybase = smem_u32(&sy[b][(lane & 15) * YSTR]) + (lane >> 4) * 16;

        #pragma unroll 4
        for (int ks = 0; ks < KSTEPS; ks++) {
            // k values: j = ks*16 + {2tg,2tg+1} and +8 (broadcast LDS)
            float4 ka = k4[ks * 8 + tg];
            float4 kb = k4[ks * 8 + 4 + tg];

            float wg0 = ex2f(fmaf(qg.x, ka.x, fmaf(qg.y, ka.y, MS2)));
            float wg1 = ex2f(fmaf(qg.x, ka.z, fmaf(qg.y, ka.w, MS2)));
            float wg2 = ex2f(fmaf(qg.x, kb.x, fmaf(qg.y, kb.y, MS2)));
            float wg3 = ex2f(fmaf(qg.x, kb.z, fmaf(qg.y, kb.w, MS2)));
            float wh0 = ex2f(fmaf(qh.x, ka.x, fmaf(qh.y, ka.y, MS2)));
            float wh1 = ex2f(fmaf(qh.x, ka.z, fmaf(qh.y, ka.w, MS2)));
            float wh2 = ex2f(fmaf(qh.x, kb.x, fmaf(qh.y, kb.y, MS2)));
            float wh3 = ex2f(fmaf(qh.x, kb.z, fmaf(qh.y, kb.w, MS2)));

            uint32_t a0 = cvt_f16x2(wg1, wg0);
            uint32_t a1 = cvt_f16x2(wh1, wh0);
            uint32_t a2 = cvt_f16x2(wg3, wg2);
            uint32_t a3 = cvt_f16x2(wh3, wh2);

            uint32_t b0, b1, b2, b3;
            ldmatrix_x4_trans(b0, b1, b2, b3, ybase + (ks * 16) * (YSTR * 2));

            mma16816(d10, d11, d12, d13, a0, a1, a2, a3, b0, b1);   // classes 0-7
            mma16816(d20, d21, d22, d23, a0, a1, a2, a3, b2, b3);   // classes 8-15
            mma16816(e0, e1, e2, e3, a0, a1, a2, a3, ONES, ONES);   // denominator
        }

        if (sc + 1 < NSC) {
            STS_CHUNK(b ^ 1);
            if (sc + 2 < NSC) LDG_CHUNK(sc + 2);
        }
        __syncthreads();
    }

    // write partials
    float* p0 = &g_pnum[((size_t)split * NT + r0) * NCLS];
    float* p1 = &g_pnum[((size_t)split * NT + r1) * NCLS];
    *reinterpret_cast<float2*>(p0 + 2 * tg)     = make_float2(d10, d11);
    *reinterpret_cast<float2*>(p0 + 8 + 2 * tg) = make_float2(d20, d21);
    *reinterpret_cast<float2*>(p1 + 2 * tg)     = make_float2(d12, d13);
    *reinterpret_cast<float2*>(p1 + 8 + 2 * tg) = make_float2(d22, d23);
    if (tg == 0) {
        g_pden[(size_t)split * NT + r0] = e0;
        g_pden[(size_t)split * NT + r1] = e2;
    }
#undef LDG_CHUNK
#undef STS_CHUNK
}

// ---------------- kernel 3: reduce splits + normalize (thread per i x class-quad) ----------------
__global__ __launch_bounds__(256) void reduce_kernel(float* __restrict__ out) {
    int idx = blockIdx.x * 256 + threadIdx.x;     // 0 .. NT*4-1
    int i   = idx >> 2;
    int tg  = idx & 3;

    float4 n = make_float4(0, 0, 0, 0);
    float d = 0.f;
    #pragma unroll
    for (int s = 0; s < NSPLIT; s++) {
        float4 a = *reinterpret_cast<const float4*>(
            &g_pnum[((size_t)s * NT + i) * NCLS + tg * 4]);
        n.x += a.x; n.y += a.y; n.z += a.z; n.w += a.w;
        d += g_pden[(size_t)s * NT + i];
    }
    float inv = 1.0f / d;
    n.x *= inv; n.y *= inv; n.z *= inv; n.w *= inv;
    *reinterpret_cast<float4*>(out + (size_t)i * NCLS + tg * 4) = n;
}

// ---------------- launch ----------------
extern "C" void kernel_launch(void* const* d_in, const int* in_sizes, int n_in,
                              void* d_out, int out_size) {
    const float* xtr = (const float*)d_in[0];   // [16384, 512]
    const float* ytr = (const float*)d_in[1];   // [16384, 16]
    const float* xt  = (const float*)d_in[2];   // [8192, 512]
    const float* A   = (const float*)d_in[3];   // [512, 2]
    float* out = (float*)d_out;                 // [8192, 16]

    proj_prep_kernel<<<PROJ_CTAS + PREP_CTAS, 256>>>(xt, xtr, A, ytr);

    dim3 grid(NT / MTILE, NSPLIT);               // 128 x 8 = 1024 CTAs
    attn_kernel<<<grid, 128>>>();

    reduce_kernel<<<NT * 4 / 256, 256>>>(out);   // 128 CTAs
}

// round 9
// speedup vs baseline: 1.1048x; 1.0081x over previous
#include <cuda_runtime.h>
#include <cuda_fp16.h>
#include <cstdint>

#define D     512
#define NTR   16384
#define NT    8192
#define NCLS  16

#define NSPLIT  8
#define JCHUNK  (NTR / NSPLIT)       // 2048
#define SCHUNK  256                  // j staged per buffer
#define NSC     (JCHUNK / SCHUNK)    // 8
#define KSTEPS  (SCHUNK / 16)        // 16 mma k-steps per staged chunk
#define MTILE   64                   // i rows per CTA (4 warps x 16)
#define YSTR    24                   // halves per padded ytr row (48B, conflict-free ldmatrix)

#define LOG2E  1.4426950408889634f
#define MS2    (-8.656170245333781f)   // -6 nats in log2 units, softmax-invariant shift

#define RPW       4                    // rows per warp in proj
#define PROJ_CTAS ((NT + NTR) / (8 * RPW))   // 768
#define PREP_CTAS (NTR / 256)                // 64

// ---------------- device scratch ----------------
__device__ float2 g_q[NT];          // q pre-scaled by log2(e)
__device__ float2 g_k[NTR];
__device__ uint4  g_y16[NTR * 2];   // fp16 ytr, 32B per row
__device__ float  g_pnum[NSPLIT * NT * NCLS];
__device__ float  g_pden[NSPLIT * NT];

// ---------------- helpers ----------------
__device__ __forceinline__ float ex2f(float x) {
    float r; asm("ex2.approx.ftz.f32 %0, %1;" : "=f"(r) : "f"(x)); return r;
}
__device__ __forceinline__ uint32_t cvt_f16x2(float hi, float lo) {
    uint32_t r; asm("cvt.rn.f16x2.f32 %0, %1, %2;" : "=r"(r) : "f"(hi), "f"(lo)); return r;
}
__device__ __forceinline__ uint32_t smem_u32(const void* p) {
    uint32_t a;
    asm("{ .reg .u64 t; cvta.to.shared.u64 t, %1; cvt.u32.u64 %0, t; }" : "=r"(a) : "l"(p));
    return a;
}
__device__ __forceinline__ void ldmatrix_x4_trans(uint32_t& r0, uint32_t& r1,
                                                  uint32_t& r2, uint32_t& r3,
                                                  uint32_t addr) {
    asm volatile("ldmatrix.sync.aligned.m8n8.x4.trans.shared.b16 {%0,%1,%2,%3}, [%4];"
                 : "=r"(r0), "=r"(r1), "=r"(r2), "=r"(r3) : "r"(addr));
}
__device__ __forceinline__ void mma16816(float& c0, float& c1, float& c2, float& c3,
                                         uint32_t a0, uint32_t a1, uint32_t a2, uint32_t a3,
                                         uint32_t b0, uint32_t b1) {
    asm volatile("mma.sync.aligned.m16n8k16.row.col.f32.f16.f16.f32 "
                 "{%0,%1,%2,%3}, {%4,%5,%6,%7}, {%8,%9}, {%0,%1,%2,%3};"
                 : "+f"(c0), "+f"(c1), "+f"(c2), "+f"(c3)
                 : "r"(a0), "r"(a1), "r"(a2), "r"(a3), "r"(b0), "r"(b1));
}

// ---------------- kernel 1: fused projections + ytr->fp16 conversion ----------------
// CTAs [0, PROJ_CTAS): 8 warps x 4 rows each (32 rows/CTA), all loads batched for MLP.
// CTAs [PROJ_CTAS, +PREP_CTAS): convert 256 ytr rows to fp16.
__global__ __launch_bounds__(256) void proj_prep_kernel(const float* __restrict__ xt,
                                                        const float* __restrict__ xtr,
                                                        const float* __restrict__ A,
                                                        const float* __restrict__ ytr) {
    int tid = threadIdx.x;

    if (blockIdx.x >= PROJ_CTAS) {
        // ---- prep branch: ytr -> fp16 ----
        int row = (blockIdx.x - PROJ_CTAS) * 256 + tid;
        const float4* src = reinterpret_cast<const float4*>(ytr + (size_t)row * NCLS);
        float4 v0 = src[0], v1 = src[1], v2 = src[2], v3 = src[3];
        uint4 o0, o1;
        o0.x = cvt_f16x2(v0.y, v0.x); o0.y = cvt_f16x2(v0.w, v0.z);
        o0.z = cvt_f16x2(v1.y, v1.x); o0.w = cvt_f16x2(v1.w, v1.z);
        o1.x = cvt_f16x2(v2.y, v2.x); o1.y = cvt_f16x2(v2.w, v2.z);
        o1.z = cvt_f16x2(v3.y, v3.x); o1.w = cvt_f16x2(v3.w, v3.z);
        g_y16[row * 2]     = o0;
        g_y16[row * 2 + 1] = o1;
        return;
    }

    // ---- proj branch: q = (xt@A)*log2e, k = xtr@A ----
    // A staged transposed so the per-lane column slice hits bank == lane (conflict-free).
    __shared__ float sA0t[D], sA1t[D];
    #pragma unroll
    for (int c = tid; c < D; c += 256) {
        float2 a = reinterpret_cast<const float2*>(A)[c];
        int idx = (c >> 7) * 128 + (c & 3) * 32 + ((c >> 2) & 31);
        sA0t[idx] = a.x; sA1t[idx] = a.y;
    }
    __syncthreads();

    int warp = tid >> 5;
    int lane = tid & 31;
    int row0 = blockIdx.x * (8 * RPW) + warp * RPW;

    const float* src;  float2* dst;  float scale;
    if (row0 < NT) { src = xt;  dst = g_q; scale = LOG2E; }
    else           { src = xtr; dst = g_k; scale = 1.0f;  row0 -= NT; }

    // hoist this lane's A slice into registers (reused across RPW rows)
    float a0[16], a1[16];
    #pragma unroll
    for (int it = 0; it < 4; it++) {
        #pragma unroll
        for (int u = 0; u < 4; u++) {
            int idx = it * 128 + u * 32 + lane;
            a0[it * 4 + u] = sA0t[idx];
            a1[it * 4 + u] = sA1t[idx];
        }
    }

    // batch ALL row loads first: 16 LDG.128 in flight per warp
    float4 xv[RPW][4];
    #pragma unroll
    for (int r = 0; r < RPW; r++) {
        const float4* xr4 = reinterpret_cast<const float4*>(src + (size_t)(row0 + r) * D);
        #pragma unroll
        for (int it = 0; it < 4; it++)
            xv[r][it] = xr4[it * 32 + lane];
    }

    // 4 independent dual-accumulator FMA chains (ILP across rows)
    float s0[RPW], s1[RPW];
    #pragma unroll
    for (int r = 0; r < RPW; r++) {
        float p0 =      xv[r][0].x * a0[0];
        float p1 =      xv[r][0].y * a0[1];
        float q0 =      xv[r][0].x * a1[0];
        float q1 =      xv[r][0].y * a1[1];
        p0 = fmaf(xv[r][0].z, a0[2],  p0);  q0 = fmaf(xv[r][0].z, a1[2],  q0);
        p1 = fmaf(xv[r][0].w, a0[3],  p1);  q1 = fmaf(xv[r][0].w, a1[3],  q1);
        p0 = fmaf(xv[r][1].x, a0[4],  p0);  q0 = fmaf(xv[r][1].x, a1[4],  q0);
        p1 = fmaf(xv[r][1].y, a0[5],  p1);  q1 = fmaf(xv[r][1].y, a1[5],  q1);
        p0 = fmaf(xv[r][1].z, a0[6],  p0);  q0 = fmaf(xv[r][1].z, a1[6],  q0);
        p1 = fmaf(xv[r][1].w, a0[7],  p1);  q1 = fmaf(xv[r][1].w, a1[7],  q1);
        p0 = fmaf(xv[r][2].x, a0[8],  p0);  q0 = fmaf(xv[r][2].x, a1[8],  q0);
        p1 = fmaf(xv[r][2].y, a0[9],  p1);  q1 = fmaf(xv[r][2].y, a1[9],  q1);
        p0 = fmaf(xv[r][2].z, a0[10], p0);  q0 = fmaf(xv[r][2].z, a1[10], q0);
        p1 = fmaf(xv[r][2].w, a0[11], p1);  q1 = fmaf(xv[r][2].w, a1[11], q1);
        p0 = fmaf(xv[r][3].x, a0[12], p0);  q0 = fmaf(xv[r][3].x, a1[12], q0);
        p1 = fmaf(xv[r][3].y, a0[13], p1);  q1 = fmaf(xv[r][3].y, a1[13], q1);
        p0 = fmaf(xv[r][3].z, a0[14], p0);  q0 = fmaf(xv[r][3].z, a1[14], q0);
        p1 = fmaf(xv[r][3].w, a0[15], p1);  q1 = fmaf(xv[r][3].w, a1[15], q1);
        s0[r] = p0 + p1;
        s1[r] = q0 + q1;
    }

    // interleaved butterfly reductions (4 independent chains hide shfl latency)
    #pragma unroll
    for (int off = 16; off > 0; off >>= 1) {
        #pragma unroll
        for (int r = 0; r < RPW; r++) {
            s0[r] += __shfl_xor_sync(0xFFFFFFFFu, s0[r], off);
            s1[r] += __shfl_xor_sync(0xFFFFFFFFu, s1[r], off);
        }
    }
    if (lane == 0) {
        #pragma unroll
        for (int r = 0; r < RPW; r++)
            dst[row0 + r] = make_float2(s0[r] * scale, s1[r] * scale);
    }
}

// ---------------- kernel 2: fp32 logits + fp32 exp + mma.sync streaming ----------------
__global__ __launch_bounds__(128, 7) void attn_kernel() {
    __shared__ float2 sk[2][SCHUNK];                         // 2 x 2KB
    __shared__ __align__(16) __half sy[2][SCHUNK * YSTR];    // 2 x 12KB (48B rows)

    int tid  = threadIdx.x;
    int wid  = tid >> 5;
    int lane = tid & 31;
    int g    = lane >> 2;
    int tg   = lane & 3;
    int split = blockIdx.y;
    int r0 = blockIdx.x * MTILE + wid * 16 + g;
    int r1 = r0 + 8;
    int j0 = split * JCHUNK;

    float2 qg = g_q[r0];
    float2 qh = g_q[r1];

    // accumulators: classes n0-7, n8-15, denominator (ones-column MMA)
    float d10 = 0, d11 = 0, d12 = 0, d13 = 0;
    float d20 = 0, d21 = 0, d22 = 0, d23 = 0;
    float e0 = 0, e1 = 0, e2 = 0, e3 = 0;
    const uint32_t ONES = 0x3C003C00u;

    // prefetch registers for staging
    float4 pk;  uint4 py0, py1, py2, py3;

#define LDG_CHUNK(sc) do {                                                   \
        int jb = j0 + (sc) * SCHUNK;                                         \
        pk = reinterpret_cast<const float4*>(g_k)[(jb >> 1) + tid];          \
        int rr = (jb + 2 * tid) * 2;                                         \
        py0 = g_y16[rr]; py1 = g_y16[rr + 1];                                \
        py2 = g_y16[rr + 2]; py3 = g_y16[rr + 3];                            \
    } while (0)

#define STS_CHUNK(b) do {                                                    \
        reinterpret_cast<float4*>(sk[b])[tid] = pk;                          \
        uint4* dr0 = reinterpret_cast<uint4*>(&sy[b][(2 * tid) * YSTR]);     \
        dr0[0] = py0; dr0[1] = py1;                                          \
        uint4* dr1 = reinterpret_cast<uint4*>(&sy[b][(2 * tid + 1) * YSTR]); \
        dr1[0] = py2; dr1[1] = py3;                                          \
    } while (0)

    LDG_CHUNK(0);
    STS_CHUNK(0);
    LDG_CHUNK(1);
    __syncthreads();

    for (int sc = 0; sc < NSC; sc++) {
        int b = sc & 1;
        const float4* k4 = reinterpret_cast<const float4*>(sk[b]);
        uint32_t ybase = smem_u32(&sy[b][(lane & 15) * YSTR]) + (lane >> 4) * 16;

        #pragma unroll 4
        for (int ks = 0; ks < KSTEPS; ks++) {
            // k values: j = ks*16 + {2tg,2tg+1} and +8 (broadcast LDS)
            float4 ka = k4[ks * 8 + tg];
            float4 kb = k4[ks * 8 + 4 + tg];

            float wg0 = ex2f(fmaf(qg.x, ka.x, fmaf(qg.y, ka.y, MS2)));
            float wg1 = ex2f(fmaf(qg.x, ka.z, fmaf(qg.y, ka.w, MS2)));
            float wg2 = ex2f(fmaf(qg.x, kb.x, fmaf(qg.y, kb.y, MS2)));
            float wg3 = ex2f(fmaf(qg.x, kb.z, fmaf(qg.y, kb.w, MS2)));
            float wh0 = ex2f(fmaf(qh.x, ka.x, fmaf(qh.y, ka.y, MS2)));
            float wh1 = ex2f(fmaf(qh.x, ka.z, fmaf(qh.y, ka.w, MS2)));
            float wh2 = ex2f(fmaf(qh.x, kb.x, fmaf(qh.y, kb.y, MS2)));
            float wh3 = ex2f(fmaf(qh.x, kb.z, fmaf(qh.y, kb.w, MS2)));

            uint32_t a0 = cvt_f16x2(wg1, wg0);
            uint32_t a1 = cvt_f16x2(wh1, wh0);
            uint32_t a2 = cvt_f16x2(wg3, wg2);
            uint32_t a3 = cvt_f16x2(wh3, wh2);

            uint32_t b0, b1, b2, b3;
            ldmatrix_x4_trans(b0, b1, b2, b3, ybase + (ks * 16) * (YSTR * 2));

            mma16816(d10, d11, d12, d13, a0, a1, a2, a3, b0, b1);   // classes 0-7
            mma16816(d20, d21, d22, d23, a0, a1, a2, a3, b2, b3);   // classes 8-15
            mma16816(e0, e1, e2, e3, a0, a1, a2, a3, ONES, ONES);   // denominator
        }

        if (sc + 1 < NSC) {
            STS_CHUNK(b ^ 1);
            if (sc + 2 < NSC) LDG_CHUNK(sc + 2);
        }
        __syncthreads();
    }

    // write partials
    float* p0 = &g_pnum[((size_t)split * NT + r0) * NCLS];
    float* p1 = &g_pnum[((size_t)split * NT + r1) * NCLS];
    *reinterpret_cast<float2*>(p0 + 2 * tg)     = make_float2(d10, d11);
    *reinterpret_cast<float2*>(p0 + 8 + 2 * tg) = make_float2(d20, d21);
    *reinterpret_cast<float2*>(p1 + 2 * tg)     = make_float2(d12, d13);
    *reinterpret_cast<float2*>(p1 + 8 + 2 * tg) = make_float2(d22, d23);
    if (tg == 0) {
        g_pden[(size_t)split * NT + r0] = e0;
        g_pden[(size_t)split * NT + r1] = e2;
    }
#undef LDG_CHUNK
#undef STS_CHUNK
}

// ---------------- kernel 3: reduce splits + normalize (thread per i x class-quad) ----------------
__global__ __launch_bounds__(256) void reduce_kernel(float* __restrict__ out) {
    int idx = blockIdx.x * 256 + threadIdx.x;     // 0 .. NT*4-1
    int i   = idx >> 2;
    int tg  = idx & 3;

    float4 n = make_float4(0, 0, 0, 0);
    float d = 0.f;
    #pragma unroll
    for (int s = 0; s < NSPLIT; s++) {
        float4 a = *reinterpret_cast<const float4*>(
            &g_pnum[((size_t)s * NT + i) * NCLS + tg * 4]);
        n.x += a.x; n.y += a.y; n.z += a.z; n.w += a.w;
        d += g_pden[(size_t)s * NT + i];
    }
    float inv = 1.0f / d;
    n.x *= inv; n.y *= inv; n.z *= inv; n.w *= inv;
    *reinterpret_cast<float4*>(out + (size_t)i * NCLS + tg * 4) = n;
}

// ---------------- launch ----------------
extern "C" void kernel_launch(void* const* d_in, const int* in_sizes, int n_in,
                              void* d_out, int out_size) {
    const float* xtr = (const float*)d_in[0];   // [16384, 512]
    const float* ytr = (const float*)d_in[1];   // [16384, 16]
    const float* xt  = (const float*)d_in[2];   // [8192, 512]
    const float* A   = (const float*)d_in[3];   // [512, 2]
    float* out = (float*)d_out;                 // [8192, 16]

    proj_prep_kernel<<<PROJ_CTAS + PREP_CTAS, 256>>>(xt, xtr, A, ytr);

    dim3 grid(NT / MTILE, NSPLIT);               // 128 x 8 = 1024 CTAs
    attn_kernel<<<grid, 128>>>();

    reduce_kernel<<<NT * 4 / 256, 256>>>(out);   // 128 CTAs
}